// round 6
// baseline (speedup 1.0000x reference)
#include <cuda_runtime.h>

// Problem constants
#define NSITES   50000
#define NPERM    12
#define NNEIGH   8
#define NODEF    64
#define INF      512
#define OUTF     64
#define LN2F     0.6931471805599453f

// Tiling
#define BM       96          // rows per block = 8 sites * 12 perms
#define SITES_PB 8
#define NTHREADS 384
#define LDA      68          // padded A row stride in floats (17 float4)

// k-major transposed weights: g_Wt[k][o] = W[o][k]
__device__ float g_Wt[INF * OUTF];

__global__ void transpose_W_kernel(const float* __restrict__ W) {
    int i = blockIdx.x * blockDim.x + threadIdx.x;   // over 32768
    if (i < INF * OUTF) {
        int k = i >> 6;        // 0..511
        int o = i & 63;        // 0..63
        g_Wt[i] = W[o * INF + k];
    }
}

__global__ __launch_bounds__(NTHREADS, 3)   // cap regs at 56 -> 3 CTAs/SM
void lcnn_main_kernel(const float* __restrict__ X,
                      const int*   __restrict__ NS,
                      const float* __restrict__ bias,
                      float*       __restrict__ out)
{
    __shared__ float A_sm[BM * LDA];       // 96*68*4 = 26112 B (reused as reduce buf)
    __shared__ float W_sm[64 * 64];        // 16384 B
    __shared__ int   idx_sm[BM * NNEIGH];  // 3072 B
    __shared__ float b_sm[OUTF];           // 256 B

    const int tid = threadIdx.x;
    const int blk = blockIdx.x;
    const long row_base = (long)blk * BM;  // global (site,perm) row

    // Load all neighbor indices for this block's 96 rows (coalesced)
    for (int i = tid; i < BM * NNEIGH; i += NTHREADS)
        idx_sm[i] = NS[row_base * NNEIGH + i];
    if (tid < OUTF) b_sm[tid] = bias[tid];

    const int tx = tid & 15;   // 0..15 : output-col group (4 cols each)
    const int ty = tid >> 4;   // 0..23 : row group (4 rows each)

    float acc[4][4];
    #pragma unroll
    for (int r = 0; r < 4; r++)
        #pragma unroll
        for (int c2 = 0; c2 < 4; c2++)
            acc[r][c2] = 0.0f;

    const float4* X4  = (const float4*)X;
    const float4* Wt4 = (const float4*)g_Wt;
    float4* A4 = (float4*)A_sm;   // row stride 17 float4
    float4* W4 = (float4*)W_sm;

    // K loop: 8 chunks of 64 (one neighbor slot per chunk)
    for (int c = 0; c < NNEIGH; c++) {
        __syncthreads();

        // Stage A: 96 rows x 16 float4 gathered rows (1536 float4, 4/thread)
        #pragma unroll
        for (int it = 0; it < 4; it++) {
            int linear = tid + it * NTHREADS;       // < 1536
            int m = linear >> 4;
            int f = linear & 15;
            int nb = idx_sm[m * NNEIGH + c];
            A4[m * 17 + f] = X4[(long)nb * 16 + f];
        }
        // Stage W chunk: k-major [64][64] direct copy (1024 float4)
        for (int linear = tid; linear < 1024; linear += NTHREADS) {
            W4[linear] = Wt4[c * 1024 + linear];
        }
        __syncthreads();

        // Register-tiled FMA, k-unrolled by 4 with vector A loads:
        // 8 LDS.128 per 64 FMA. Array views avoid SEL chains / extra regs.
        #pragma unroll
        for (int k = 0; k < 64; k += 4) {
            const int kq = k >> 2;
            float4 a0v = A4[(ty * 4 + 0) * 17 + kq];
            float4 a1v = A4[(ty * 4 + 1) * 17 + kq];
            float4 a2v = A4[(ty * 4 + 2) * 17 + kq];
            float4 a3v = A4[(ty * 4 + 3) * 17 + kq];
            const float* a0 = (const float*)&a0v;
            const float* a1 = (const float*)&a1v;
            const float* a2 = (const float*)&a2v;
            const float* a3 = (const float*)&a3v;
            #pragma unroll
            for (int kk = 0; kk < 4; kk++) {
                float4 w = W4[(k + kk) * 16 + tx];
                float e0 = a0[kk], e1 = a1[kk], e2 = a2[kk], e3 = a3[kk];
                acc[0][0] += e0 * w.x; acc[0][1] += e0 * w.y;
                acc[0][2] += e0 * w.z; acc[0][3] += e0 * w.w;
                acc[1][0] += e1 * w.x; acc[1][1] += e1 * w.y;
                acc[1][2] += e1 * w.z; acc[1][3] += e1 * w.w;
                acc[2][0] += e2 * w.x; acc[2][1] += e2 * w.y;
                acc[2][2] += e2 * w.z; acc[2][3] += e2 * w.w;
                acc[3][0] += e3 * w.x; acc[3][1] += e3 * w.y;
                acc[3][2] += e3 * w.z; acc[3][3] += e3 * w.w;
            }
        }
    }

    // Epilogue: bias + shifted-softplus, partial sum over this thread's 4 perms.
    // Each thread's 4 rows (ty*4 .. ty*4+3) lie inside ONE site (4 | 12 pattern).
    float part[4];
    #pragma unroll
    for (int c2 = 0; c2 < 4; c2++) {
        float bv = b_sm[tx * 4 + c2];
        float s = 0.0f;
        #pragma unroll
        for (int r = 0; r < 4; r++) {
            float x = acc[r][c2] + bv;
            // stable softplus
            float sp = fmaxf(x, 0.0f) + __logf(1.0f + __expf(-fabsf(x)));
            s += sp - LN2F;
        }
        part[c2] = s;
    }

    __syncthreads();            // done with A_sm as GEMM tile
    float* red = A_sm;          // reuse: [24][64] partials
    #pragma unroll
    for (int c2 = 0; c2 < 4; c2++)
        red[ty * 64 + tx * 4 + c2] = part[c2];
    __syncthreads();

    // Combine 3 ty-groups per site (perms 0-3, 4-7, 8-11); coalesced store.
    // 512 outputs per block, 384 threads -> strided loop.
    for (int i = tid; i < SITES_PB * OUTF; i += NTHREADS) {
        int s   = i >> 6;
        int col = i & 63;
        float v = red[(3 * s + 0) * 64 + col]
                + red[(3 * s + 1) * 64 + col]
                + red[(3 * s + 2) * 64 + col];
        out[((long)blk * SITES_PB + s) * OUTF + col] = v;
    }
}

extern "C" void kernel_launch(void* const* d_in, const int* in_sizes, int n_in,
                              void* d_out, int out_size) {
    const float* X  = (const float*)d_in[0];   // X_sites (50000,64) f32
    const int*   NS = (const int*)  d_in[1];   // X_NSs   (50000,12,8) i32
    const float* W  = (const float*)d_in[2];   // W       (64,512) f32
    const float* b  = (const float*)d_in[3];   // b       (64,) f32
    float* out = (float*)d_out;                // (50000,64) f32

    transpose_W_kernel<<<(INF * OUTF + 255) / 256, 256>>>(W);
    lcnn_main_kernel<<<NSITES / SITES_PB, NTHREADS>>>(X, NS, b, out);
}

// round 7
// speedup vs baseline: 1.2699x; 1.2699x over previous
#include <cuda_runtime.h>

// Problem constants
#define NSITES   50000
#define NPERM    12
#define NNEIGH   8
#define NODEF    64
#define INF      512
#define OUTF     64
#define LN2F     0.6931471805599453f

// Tiling: 192 rows = 16 sites, 192 threads, 8x8 micro-tile
#define BM       192
#define SITES_PB 16
#define NTHREADS 192
#define LDA      68          // padded A row stride in floats (17 float4)

// k-major transposed weights: g_Wt[k][o] = W[o][k]
__device__ float g_Wt[INF * OUTF];

__global__ void transpose_W_kernel(const float* __restrict__ W) {
    int i = blockIdx.x * blockDim.x + threadIdx.x;   // over 32768
    if (i < INF * OUTF) {
        int k = i >> 6;        // 0..511
        int o = i & 63;        // 0..63
        g_Wt[i] = W[o * INF + k];
    }
}

__global__ __launch_bounds__(NTHREADS)
void lcnn_main_kernel(const float* __restrict__ X,
                      const int*   __restrict__ NS,
                      const float* __restrict__ bias,
                      float*       __restrict__ out)
{
    __shared__ float A_sm[BM * LDA];       // 192*68*4 = 52224 B (reused as reduce buf)
    __shared__ float W_sm[64 * 64];        // 16384 B
    __shared__ int   idx_sm[BM * NNEIGH];  // 6144 B
    __shared__ float b_sm[OUTF];           // 256 B

    const int tid = threadIdx.x;
    const int blk = blockIdx.x;
    const long row_base = (long)blk * BM;  // global (site,perm) row

    // Load all neighbor indices for this block's 192 rows (coalesced)
    for (int i = tid; i < BM * NNEIGH; i += NTHREADS)
        idx_sm[i] = NS[row_base * NNEIGH + i];
    if (tid < OUTF) b_sm[tid] = bias[tid];

    const int tx  = tid & 7;   // 0..7  : output-col group (8 cols each)
    const int tyr = tid >> 3;  // 0..23 : row group (8 rows each)

    float acc[8][8];
    #pragma unroll
    for (int r = 0; r < 8; r++)
        #pragma unroll
        for (int c2 = 0; c2 < 8; c2++)
            acc[r][c2] = 0.0f;

    const float4* X4  = (const float4*)X;
    const float4* Wt4 = (const float4*)g_Wt;
    float4* A4 = (float4*)A_sm;   // row stride 17 float4
    float4* W4 = (float4*)W_sm;

    // K loop: 8 chunks of 64 (one neighbor slot per chunk)
    for (int c = 0; c < NNEIGH; c++) {
        __syncthreads();

        // Stage A: 192 rows x 16 float4 gathered rows (3072 float4, 16/thread)
        #pragma unroll
        for (int it = 0; it < 16; it++) {
            int linear = tid + it * NTHREADS;       // < 3072
            int m = linear >> 4;
            int f = linear & 15;
            int nb = idx_sm[m * NNEIGH + c];
            A4[m * 17 + f] = X4[(long)nb * 16 + f];
        }
        // Stage W chunk: k-major [64][64] direct copy (1024 float4)
        for (int linear = tid; linear < 1024; linear += NTHREADS) {
            W4[linear] = Wt4[c * 1024 + linear];
        }
        __syncthreads();

        // 8x8 register micro-tile: per k, 8 LDS.32 (A) + 2 LDS.128 (W) per 64 FMA
        #pragma unroll 8
        for (int k = 0; k < 64; k++) {
            float4 w0 = W4[k * 16 + tx * 2 + 0];
            float4 w1 = W4[k * 16 + tx * 2 + 1];
            float a[8];
            #pragma unroll
            for (int r = 0; r < 8; r++)
                a[r] = A_sm[(tyr * 8 + r) * LDA + k];
            #pragma unroll
            for (int r = 0; r < 8; r++) {
                acc[r][0] += a[r] * w0.x; acc[r][1] += a[r] * w0.y;
                acc[r][2] += a[r] * w0.z; acc[r][3] += a[r] * w0.w;
                acc[r][4] += a[r] * w1.x; acc[r][5] += a[r] * w1.y;
                acc[r][6] += a[r] * w1.z; acc[r][7] += a[r] * w1.w;
            }
        }
    }

    // Epilogue: bias + shifted-softplus per element, write to smem reduce buffer.
    // (8-row groups straddle sites now, so the perm-sum is done entirely in smem.)
    __syncthreads();                  // done with A_sm as GEMM tile
    float* red = A_sm;                // reuse: [192][64] post-softplus values
    #pragma unroll
    for (int r = 0; r < 8; r++) {
        #pragma unroll
        for (int c2 = 0; c2 < 8; c2++) {
            float x = acc[r][c2] + b_sm[tx * 8 + c2];
            float sp = fmaxf(x, 0.0f) + __logf(1.0f + __expf(-fabsf(x)));
            red[(tyr * 8 + r) * 64 + tx * 8 + c2] = sp - LN2F;
        }
    }
    __syncthreads();

    // Sum 12 perms per site; 16 sites * 64 cols = 1024 outputs, strided over 192 threads.
    for (int i = tid; i < SITES_PB * OUTF; i += NTHREADS) {
        int s   = i >> 6;
        int col = i & 63;
        float v = 0.0f;
        #pragma unroll
        for (int p = 0; p < NPERM; p++)
            v += red[(s * NPERM + p) * 64 + col];
        out[((long)blk * SITES_PB + s) * OUTF + col] = v;
    }
}

extern "C" void kernel_launch(void* const* d_in, const int* in_sizes, int n_in,
                              void* d_out, int out_size) {
    const float* X  = (const float*)d_in[0];   // X_sites (50000,64) f32
    const int*   NS = (const int*)  d_in[1];   // X_NSs   (50000,12,8) i32
    const float* W  = (const float*)d_in[2];   // W       (64,512) f32
    const float* b  = (const float*)d_in[3];   // b       (64,) f32
    float* out = (float*)d_out;                // (50000,64) f32

    transpose_W_kernel<<<(INF * OUTF + 255) / 256, 256>>>(W);
    lcnn_main_kernel<<<NSITES / SITES_PB, NTHREADS>>>(X, NS, b, out);
}

// round 11
// speedup vs baseline: 4.1551x; 3.2721x over previous
#include <cuda_runtime.h>
#include <cuda_bf16.h>
#include <cstdint>

#define NSITES   50000
#define NPERM    12
#define NNEIGH   8
#define INF      512
#define OUTF     64
#define LN2F     0.6931471805599453f

#define TOTROWS  (NSITES * NPERM)                  // 600000
#define BM       256
#define NBLOCKS  ((TOTROWS + BM - 1) / BM)         // 2344
#define NTHREADS 256
#define NCHUNK   8
#define WS       72        // padded smem row stride in bf16 elems (144 B)

// ---------------- SMEM layout (bytes, dynamic) ----------------
#define SM_BIAS  0                          // 64 f32 = 256 B
#define SM_IDX   256                        // 256*8 int = 8192 B
#define SM_WHI   8448                       // 64*144 = 9216 B
#define SM_WLO   (SM_WHI + 9216)            // 17664
#define SM_AHI   26880                      // 256*144 = 36864 B
#define SM_ALO   (SM_AHI + 36864)           // 63744
#define SM_TOTAL 100608
#define SM_RED   SM_AHI                     // epilogue reuse: 256*64 f32 = 65536 B

// ---------------- global split buffers ----------------
__device__ __nv_bfloat16 g_Whi[NCHUNK * 64 * 64];   // [c][n][kk], kk contiguous
__device__ __nv_bfloat16 g_Wlo[NCHUNK * 64 * 64];
__device__ __nv_bfloat16 g_Xhi[NSITES * 64];
__device__ __nv_bfloat16 g_Xlo[NSITES * 64];

// ---------------- pre-kernels ----------------
__global__ void split_W_kernel(const float* __restrict__ W) {
    int i = blockIdx.x * blockDim.x + threadIdx.x;
    if (i < OUTF * INF) {
        int n = i >> 9, k = i & 511, c = k >> 6, kk = k & 63;
        float v = W[i];
        __nv_bfloat16 h = __float2bfloat16(v);
        float r = v - __bfloat162float(h);
        int j = c * 4096 + n * 64 + kk;
        g_Whi[j] = h;
        g_Wlo[j] = __float2bfloat16(r);
    }
}
__global__ void split_X_kernel(const float* __restrict__ X) {
    int i = blockIdx.x * blockDim.x + threadIdx.x;
    if (i < NSITES * 64) {
        float v = X[i];
        __nv_bfloat16 h = __float2bfloat16(v);
        g_Xhi[i] = h;
        g_Xlo[i] = __float2bfloat16(v - __bfloat162float(h));
    }
}
__global__ void zero_out_kernel(float* __restrict__ out) {
    int i = blockIdx.x * blockDim.x + threadIdx.x;
    if (i < NSITES * OUTF) out[i] = 0.0f;
}

// ---------------- mma helper ----------------
__device__ __forceinline__ void mma_bf16(float* d, const uint32_t* a,
                                         uint32_t b0, uint32_t b1) {
    asm volatile(
        "mma.sync.aligned.m16n8k16.row.col.f32.bf16.bf16.f32 "
        "{%0,%1,%2,%3}, {%4,%5,%6,%7}, {%8,%9}, {%0,%1,%2,%3};\n"
        : "+f"(d[0]), "+f"(d[1]), "+f"(d[2]), "+f"(d[3])
        : "r"(a[0]), "r"(a[1]), "r"(a[2]), "r"(a[3]), "r"(b0), "r"(b1));
}
__device__ __forceinline__ uint32_t lds32(const __nv_bfloat16* p) {
    return *(const uint32_t*)p;
}

// ---------------- main kernel ----------------
__global__ __launch_bounds__(NTHREADS)
void lcnn_mma_kernel(const int* __restrict__ NS,
                     const float* __restrict__ bias,
                     float* __restrict__ out)
{
    extern __shared__ char smem[];
    const int tid = threadIdx.x;
    const int wid = tid >> 5;     // 0..7
    const int lid = tid & 31;
    const int g   = lid >> 2;     // 0..7
    const int tg  = lid & 3;      // 0..3
    const int blk = blockIdx.x;

    const int R0    = blk * BM;
    const int valid = min(BM, TOTROWS - R0);

    if (tid < OUTF) *(float*)(smem + SM_BIAS + tid * 4) = bias[tid];

    int* idx_sm = (int*)(smem + SM_IDX);
    for (int i = tid; i < BM * NNEIGH; i += NTHREADS)
        idx_sm[i] = (i < valid * NNEIGH) ? NS[(long)R0 * NNEIGH + i] : 0;

    __nv_bfloat16* Ahi = (__nv_bfloat16*)(smem + SM_AHI);
    __nv_bfloat16* Alo = (__nv_bfloat16*)(smem + SM_ALO);
    __nv_bfloat16* Whi = (__nv_bfloat16*)(smem + SM_WHI);
    __nv_bfloat16* Wlo = (__nv_bfloat16*)(smem + SM_WLO);
    uint4* A4h = (uint4*)Ahi;     // row stride 9 uint4
    uint4* A4l = (uint4*)Alo;
    uint4* W4h = (uint4*)Whi;
    uint4* W4l = (uint4*)Wlo;
    const uint4* Xhi4 = (const uint4*)g_Xhi;
    const uint4* Xlo4 = (const uint4*)g_Xlo;
    const uint4* GWh4 = (const uint4*)g_Whi;
    const uint4* GWl4 = (const uint4*)g_Wlo;

    const int wr = wid * 32;      // warp row base

    float acc[2][8][4];
    #pragma unroll
    for (int mt = 0; mt < 2; mt++)
        #pragma unroll
        for (int nt = 0; nt < 8; nt++)
            #pragma unroll
            for (int e = 0; e < 4; e++)
                acc[mt][nt][e] = 0.0f;

    for (int c = 0; c < NCHUNK; c++) {
        __syncthreads();
        // stage A chunk c (gather): 256 rows x 8 uint4, hi + lo
        #pragma unroll
        for (int it = 0; it < 8; it++) {
            int linear = tid + it * NTHREADS;       // < 2048
            int m = linear >> 3, u = linear & 7;
            int nb = idx_sm[m * NNEIGH + c];
            A4h[m * 9 + u] = Xhi4[nb * 8 + u];
            A4l[m * 9 + u] = Xlo4[nb * 8 + u];
        }
        // stage W chunk c: 64 rows x 8 uint4, hi + lo
        #pragma unroll
        for (int it = 0; it < 2; it++) {
            int u = tid + it * NTHREADS;            // < 512
            int n = u >> 3, uu = u & 7;
            W4h[n * 9 + uu] = GWh4[c * 512 + u];
            W4l[n * 9 + uu] = GWl4[c * 512 + u];
        }
        __syncthreads();

        #pragma unroll
        for (int ks = 0; ks < 4; ks++) {
            const int K = ks * 16;
            uint32_t ah[2][4], al[2][4];
            #pragma unroll
            for (int mt = 0; mt < 2; mt++) {
                const int r0 = wr + mt * 16 + g;
                ah[mt][0] = lds32(&Ahi[(r0    ) * WS + K + 2 * tg]);
                ah[mt][1] = lds32(&Ahi[(r0 + 8) * WS + K + 2 * tg]);
                ah[mt][2] = lds32(&Ahi[(r0    ) * WS + K + 8 + 2 * tg]);
                ah[mt][3] = lds32(&Ahi[(r0 + 8) * WS + K + 8 + 2 * tg]);
                al[mt][0] = lds32(&Alo[(r0    ) * WS + K + 2 * tg]);
                al[mt][1] = lds32(&Alo[(r0 + 8) * WS + K + 2 * tg]);
                al[mt][2] = lds32(&Alo[(r0    ) * WS + K + 8 + 2 * tg]);
                al[mt][3] = lds32(&Alo[(r0 + 8) * WS + K + 8 + 2 * tg]);
            }
            #pragma unroll
            for (int nt = 0; nt < 8; nt++) {
                const int nr = nt * 8 + g;
                uint32_t bh0 = lds32(&Whi[nr * WS + K + 2 * tg]);
                uint32_t bh1 = lds32(&Whi[nr * WS + K + 8 + 2 * tg]);
                uint32_t bl0 = lds32(&Wlo[nr * WS + K + 2 * tg]);
                uint32_t bl1 = lds32(&Wlo[nr * WS + K + 8 + 2 * tg]);
                mma_bf16(acc[0][nt], ah[0], bh0, bh1);
                mma_bf16(acc[1][nt], ah[1], bh0, bh1);
                mma_bf16(acc[0][nt], ah[0], bl0, bl1);
                mma_bf16(acc[1][nt], ah[1], bl0, bl1);
                mma_bf16(acc[0][nt], al[0], bh0, bh1);
                mma_bf16(acc[1][nt], al[1], bh0, bh1);
            }
        }
    }

    // Epilogue: bias + shifted softplus -> smem red buffer [256][64] f32
    __syncthreads();
    float* red = (float*)(smem + SM_RED);
    const float* bsm = (const float*)(smem + SM_BIAS);
    #pragma unroll
    for (int mt = 0; mt < 2; mt++) {
        #pragma unroll
        for (int nt = 0; nt < 8; nt++) {
            const int col = nt * 8 + 2 * tg;
            const float b0 = bsm[col], b1 = bsm[col + 1];
            const int r0 = wr + mt * 16 + g;
            float x, s0, s1;
            x = acc[mt][nt][0] + b0;
            s0 = fmaxf(x, 0.0f) + __logf(1.0f + __expf(-fabsf(x))) - LN2F;
            x = acc[mt][nt][1] + b1;
            s1 = fmaxf(x, 0.0f) + __logf(1.0f + __expf(-fabsf(x))) - LN2F;
            *(float2*)&red[r0 * 64 + col] = make_float2(s0, s1);
            x = acc[mt][nt][2] + b0;
            s0 = fmaxf(x, 0.0f) + __logf(1.0f + __expf(-fabsf(x))) - LN2F;
            x = acc[mt][nt][3] + b1;
            s1 = fmaxf(x, 0.0f) + __logf(1.0f + __expf(-fabsf(x))) - LN2F;
            *(float2*)&red[(r0 + 8) * 64 + col] = make_float2(s0, s1);
        }
    }
    __syncthreads();

    // Per-site perm sums. Sites can straddle tile boundaries -> <=2 atomic
    // contributions per output; float add of 2 terms is order-independent.
    {
        int s0 = R0 / NPERM;
        int s1 = (R0 + valid - 1) / NPERM;
        int nout = (s1 - s0 + 1) * OUTF;
        for (int i = tid; i < nout; i += NTHREADS) {
            int site = s0 + (i >> 6);
            int col  = i & 63;
            int rbeg = max(site * NPERM, R0);
            int rend = min(site * NPERM + NPERM, R0 + valid);
            float v = 0.0f;
            for (int r = rbeg; r < rend; r++)
                v += red[(r - R0) * 64 + col];
            atomicAdd(&out[(long)site * OUTF + col], v);
        }
    }
}

extern "C" void kernel_launch(void* const* d_in, const int* in_sizes, int n_in,
                              void* d_out, int out_size) {
    const float* X  = (const float*)d_in[0];   // X_sites (50000,64) f32
    const int*   NS = (const int*)  d_in[1];   // X_NSs   (50000,12,8) i32
    const float* W  = (const float*)d_in[2];   // W       (64,512) f32
    const float* b  = (const float*)d_in[3];   // b       (64,) f32
    float* out = (float*)d_out;                // (50000,64) f32

    cudaFuncSetAttribute(lcnn_mma_kernel,
                         cudaFuncAttributeMaxDynamicSharedMemorySize, SM_TOTAL);

    split_W_kernel<<<(OUTF * INF + 255) / 256, 256>>>(W);
    split_X_kernel<<<(NSITES * 64 + 255) / 256, 256>>>(X);
    zero_out_kernel<<<(NSITES * OUTF + 255) / 256, 256>>>(out);
    lcnn_mma_kernel<<<NBLOCKS, NTHREADS, SM_TOTAL>>>(NS, b, out);
}